// round 12
// baseline (speedup 1.0000x reference)
#include <cuda_runtime.h>
#include <cstdint>

#define JAX_PARTITIONABLE 1

#define BB 16
#define KG 50
#define AA 9
#define HWV 4096
#define NN 36864                      // 9*4096
#define NBLK 72                       // main/labels blocks per batch (128 thr each)
#define LBL_SZ (BB*AA*HWV)            // 589824
#define CH_SZ  (BB*36*HWV)            // 2359296
#define NT 1024

// ---------------- scratch -----------------------------------------------------
__device__ unsigned g_part[BB*NBLK*KG]; // per-block per-GT max (bits), overwritten each replay
__device__ float g_vb[BB*NN];           // per-anchor best IoU (rounded)
__device__ float g_lbl[BB*NN];          // indexed by m = a*4096 + s
__device__ unsigned char g_arg[BB*NN];
__device__ float g_uw[BB];
__device__ int  g_cnt[BB*2];            // fg/bg candidate counts (zeroed by main)
__device__ int  g_hist[BB*2*4096];      // rng-bucket histogram (zeroed by main, filled by labels)
__device__ int2 g_cand[BB*2*NN];        // .x = (n_orig<<16)|m, .y = rng23

__constant__ float c_anch[9][4] = {
  {-84.f,-40.f,99.f,55.f},
  {-176.f,-88.f,191.f,103.f},
  {-360.f,-184.f,375.f,199.f},
  {-56.f,-56.f,71.f,71.f},
  {-120.f,-120.f,135.f,135.f},
  {-248.f,-248.f,263.f,263.f},
  {-36.f,-80.f,51.f,95.f},
  {-80.f,-168.f,95.f,183.f},
  {-168.f,-344.f,183.f,359.f}
};

// ---------------- threefry-2x32 (20 rounds), matches JAX ----------------------
__host__ __device__ inline void tf2x32(unsigned k0, unsigned k1,
                                       unsigned x0, unsigned x1,
                                       unsigned &o0, unsigned &o1) {
  unsigned ks2 = k0 ^ k1 ^ 0x1BD11BDAu;
#define TF_R(r) { x0 += x1; x1 = (x1<<(r))|(x1>>(32-(r))); x1 ^= x0; }
  x0 += k0; x1 += k1;
  TF_R(13) TF_R(15) TF_R(26) TF_R(6)
  x0 += k1; x1 += ks2 + 1u;
  TF_R(17) TF_R(29) TF_R(16) TF_R(24)
  x0 += ks2; x1 += k0 + 2u;
  TF_R(13) TF_R(15) TF_R(26) TF_R(6)
  x0 += k0; x1 += k1 + 3u;
  TF_R(17) TF_R(29) TF_R(16) TF_R(24)
  x0 += k1; x1 += ks2 + 4u;
  TF_R(13) TF_R(15) TF_R(26) TF_R(6)
  x0 += ks2; x1 += k0 + 5u;
#undef TF_R
  o0 = x0; o1 = x1;
}

__device__ inline unsigned rng23(unsigned k0, unsigned k1, unsigned n) {
#if JAX_PARTITIONABLE
  unsigned o0, o1; tf2x32(k0, k1, 0u, n, o0, o1);
  return (o0 ^ o1) >> 9;
#else
  const unsigned half = NN/2;
  unsigned o0, o1;
  if (n < half) { tf2x32(k0, k1, n, n + half, o0, o1); return o0 >> 9; }
  tf2x32(k0, k1, n - half, n, o0, o1); return o1 >> 9;
#endif
}

struct Keys { unsigned k[BB][4]; };

// ---------------- kernels -----------------------------------------------------

// Pass 1: per-anchor argmax (vb, barg) + per-block per-GT watermark max.
// 128-thread blocks: each covers one anchor type x 8 rows.
__global__ __launch_bounds__(128) void main_kernel(const float* __restrict__ gt,
                                                   const float* __restrict__ iminfo) {
  int b = blockIdx.y, t = threadIdx.x;
  int bx = blockIdx.x;
  int m0 = (bx * 128 + t) * 4;
  int a  = bx >> 3;                          // 8 blocks per anchor type
  int base_row = (bx & 7) * 8;               // 8 rows per block
  __shared__ float4 sbox[KG];
  __shared__ float sarea[KG];
  __shared__ unsigned smax[KG];
  __shared__ unsigned long long rowm[8], colm[16];
  if (t < KG) {
    const float* g = gt + (b*KG + t)*5;
    float x1 = g[0], y1 = g[1], x2 = g[2], y2 = g[3];
    sbox[t] = make_float4(x1, y1, x2, y2);
    sarea[t] = __fmul_rn(__fadd_rn(__fsub_rn(x2, x1), 1.f),
                         __fadd_rn(__fsub_rn(y2, y1), 1.f));
    smax[t] = 0u;
  }
  if (bx == 0 && t < 2) g_cnt[b*2 + t] = 0;
  {   // zero rng histogram (consumed by subsample after labels fills it)
    int gid = (b*NBLK + bx)*128 + t;
    if (gid < BB*2*4096) g_hist[gid] = 0;
  }
  __syncthreads();
  cudaTriggerProgrammaticLaunchCompletion();   // let labels start early
  float c0 = c_anch[a][0], c1 = c_anch[a][1], c2 = c_anch[a][2], c3 = c_anch[a][3];
  if (t < 8) {              // row band masks (y)
    float y1r = c1 + (float)((base_row + t) * 16);
    float y2r = c3 + (float)((base_row + t) * 16);
    unsigned long long mm = 0ull;
    for (int k = 0; k < KG; k++) {
      float4 gb = sbox[k];
      if (!(gb.y - y2r >= 1.f || y1r - gb.w >= 1.f)) mm |= 1ull << k;
    }
    rowm[t] = mm;
  } else if (t < 24) {      // column-group band masks (x)
    int g4 = t - 8;
    float x1g = c0 + (float)((g4 * 4) * 16);
    float x2g = c2 + (float)((g4 * 4 + 3) * 16);
    unsigned long long mm = 0ull;
    for (int k = 0; k < KG; k++) {
      float4 gb = sbox[k];
      if (!(gb.x - x2g >= 1.f || x1g - gb.z >= 1.f)) mm |= 1ull << k;
    }
    colm[g4] = mm;
  }
  __syncthreads();
  float imh = iminfo[0], imw = iminfo[1];
  int s0 = m0 & 4095;
  int r = (s0 >> 6) - base_row;
  int g4 = (s0 & 63) >> 2;
  float ax1[4], ay1[4], ax2[4], ay2[4], aarea[4];
  bool ins[4]; bool any = false;
  float bi[4], bd[4]; int barg[4];
#pragma unroll
  for (int j = 0; j < 4; j++) {
    int s = s0 + j;
    float fx = (float)((s & 63) * 16);
    float fy = (float)((s >> 6) * 16);
    ax1[j] = __fadd_rn(c0, fx); ay1[j] = __fadd_rn(c1, fy);
    ax2[j] = __fadd_rn(c2, fx); ay2[j] = __fadd_rn(c3, fy);
    aarea[j] = __fmul_rn(__fadd_rn(__fsub_rn(ax2[j], ax1[j]), 1.f),
                         __fadd_rn(__fsub_rn(ay2[j], ay1[j]), 1.f));
    ins[j] = (ax1[j] >= 0.f) && (ay1[j] >= 0.f) && (ax2[j] < imw) && (ay2[j] < imh);
    any |= ins[j];
    bi[j] = 0.f; bd[j] = 1.f; barg[j] = 0;
  }
  if (any) {
    unsigned long long mask = rowm[r] & colm[g4];
    while (mask) {
      int k = __ffsll(mask) - 1;
      mask &= mask - 1;
      float4 gb = sbox[k];
      float ga = sarea[k];
#pragma unroll
      for (int j = 0; j < 4; j++) {
        if (!ins[j]) continue;
        float ix = fmaxf(0.f, __fadd_rn(__fsub_rn(fminf(ax2[j], gb.z), fmaxf(ax1[j], gb.x)), 1.f));
        float iy = fmaxf(0.f, __fadd_rn(__fsub_rn(fminf(ay2[j], gb.w), fmaxf(ay1[j], gb.y)), 1.f));
        float inter = __fmul_rn(ix, iy);
        if (inter <= 0.f) continue;
        float den = __fsub_rn(__fadd_rn(aarea[j], ga), inter);
        // per-GT watermark max (inside anchors only)
        unsigned wmb = smax[k];
        float wm = __uint_as_float(wmb);
        if (__fmul_rn(inter, 1.000004f) >= __fmul_rn(wm, den)) {
          unsigned v = __float_as_uint(__fdiv_rn(inter, den));
          if (v > wmb) atomicMax(&smax[k], v);
        }
        // per-anchor argmax via fraction compare + exact fallback in window
        float L = __fmul_rn(inter, bd[j]), R = __fmul_rn(bi[j], den);
        if (L > __fmul_rn(R, 1.000004f)) { bi[j] = inter; bd[j] = den; barg[j] = k; }
        else if (__fmul_rn(L, 1.000004f) >= R) {
          if (__fdiv_rn(inter, den) > __fdiv_rn(bi[j], bd[j])) {
            bi[j] = inter; bd[j] = den; barg[j] = k;
          }
        }
      }
    }
  }
  __syncthreads();
  if (t < KG) g_part[(b*NBLK + bx)*KG + t] = smax[t];
  float vb[4];
#pragma unroll
  for (int j = 0; j < 4; j++)
    vb[j] = (bi[j] > 0.f) ? __fdiv_rn(bi[j], bd[j]) : 0.f;
  *reinterpret_cast<float4*>(g_vb + b*NN + m0) = make_float4(vb[0], vb[1], vb[2], vb[3]);
  *reinterpret_cast<uchar4*>(g_arg + b*NN + m0) =
      make_uchar4((unsigned char)barg[0], (unsigned char)barg[1],
                  (unsigned char)barg[2], (unsigned char)barg[3]);
}

__device__ __forceinline__ void emit_cand(bool pred, int b, int cat,
                                          unsigned kk0, unsigned kk1,
                                          unsigned n, unsigned m, int lane) {
  unsigned msk = __ballot_sync(0xffffffffu, pred);
  if (!msk) return;
  unsigned v = 0;
  if (pred) v = rng23(kk0, kk1, n);
  int leader = __ffs(msk) - 1;
  int base = 0;
  if (lane == leader) base = atomicAdd(&g_cnt[b*2 + cat], __popc(msk));
  base = __shfl_sync(0xffffffffu, base, leader);
  if (pred) {
    int pos = base + __popc(msk & ((1u << lane) - 1u));
    g_cand[(b*2 + cat)*NN + pos] = make_int2((int)((n << 16) | m), (int)v);
    atomicAdd(&g_hist[(b*2 + cat)*4096 + (v >> 11)], 1);   // histogram at emission
  }
}

// Pass 2 (light): labels from vb + tiny is_best check restricted to k's whose
// global max was achieved inside THIS block (kbm). Prologue (gt-only) runs
// BEFORE the grid-dependency sync so it overlaps main's tail under PDL.
__global__ __launch_bounds__(128) void labels_kernel(const float* __restrict__ gt,
                                                     const float* __restrict__ iminfo,
                                                     Keys keys) {
  int b = blockIdx.y, t = threadIdx.x;
  int bx = blockIdx.x;
  int m0 = (bx * 128 + t) * 4;
  int a  = bx >> 3;
  int base_row = (bx & 7) * 8;
  __shared__ float4 sbox[KG];
  __shared__ float sarea[KG];
  __shared__ float sgm[KG];
  __shared__ unsigned s_kbm[2];
  __shared__ unsigned long long rowm[8], colm[16];
  // ---- Phase A: input-only setup (overlaps producer under PDL) ----
  if (t < KG) {
    const float* g = gt + (b*KG + t)*5;
    float x1 = g[0], y1 = g[1], x2 = g[2], y2 = g[3];
    sbox[t] = make_float4(x1, y1, x2, y2);
    sarea[t] = __fmul_rn(__fadd_rn(__fsub_rn(x2, x1), 1.f),
                         __fadd_rn(__fsub_rn(y2, y1), 1.f));
  }
  if (t >= KG && t < KG+2) s_kbm[t - KG] = 0u;
  __syncthreads();
  float c0 = c_anch[a][0], c1 = c_anch[a][1], c2 = c_anch[a][2], c3 = c_anch[a][3];
  if (t < 8) {
    float y1r = c1 + (float)((base_row + t) * 16);
    float y2r = c3 + (float)((base_row + t) * 16);
    unsigned long long mm = 0ull;
    for (int k = 0; k < KG; k++) {
      float4 gb = sbox[k];
      if (!(gb.y - y2r >= 1.f || y1r - gb.w >= 1.f)) mm |= 1ull << k;
    }
    rowm[t] = mm;
  } else if (t < 24) {
    int g4 = t - 8;
    float x1g = c0 + (float)((g4 * 4) * 16);
    float x2g = c2 + (float)((g4 * 4 + 3) * 16);
    unsigned long long mm = 0ull;
    for (int k = 0; k < KG; k++) {
      float4 gb = sbox[k];
      if (!(gb.x - x2g >= 1.f || x1g - gb.z >= 1.f)) mm |= 1ull << k;
    }
    colm[g4] = mm;
  }
  float imh = iminfo[0], imw = iminfo[1];
  int s0 = m0 & 4095;
  int r = (s0 >> 6) - base_row;
  int g4 = (s0 & 63) >> 2;
  float ax1[4], ay1[4], ax2[4], ay2[4], aarea[4];
  bool ins[4]; bool any = false; bool isb[4];
#pragma unroll
  for (int j = 0; j < 4; j++) {
    int s = s0 + j;
    float fx = (float)((s & 63) * 16);
    float fy = (float)((s >> 6) * 16);
    ax1[j] = __fadd_rn(c0, fx); ay1[j] = __fadd_rn(c1, fy);
    ax2[j] = __fadd_rn(c2, fx); ay2[j] = __fadd_rn(c3, fy);
    aarea[j] = __fmul_rn(__fadd_rn(__fsub_rn(ax2[j], ax1[j]), 1.f),
                         __fadd_rn(__fsub_rn(ay2[j], ay1[j]), 1.f));
    ins[j] = (ax1[j] >= 0.f) && (ay1[j] >= 0.f) && (ax2[j] < imw) && (ay2[j] < imh);
    any |= ins[j];
    isb[j] = false;
  }
  // ---- wait for main, then consume its outputs ----
  cudaGridDependencySynchronize();
  cudaTriggerProgrammaticLaunchCompletion();
  bool flag = false;
  if (t < KG) {
    unsigned mx = 0u;
    const unsigned* pp = g_part + b*NBLK*KG + t;
#pragma unroll 8
    for (int i = 0; i < NBLK; i++) mx = max(mx, pp[i*KG]);
    sgm[t] = __uint_as_float(mx);             // mx==0 handled by flag (no match possible)
    flag = (mx != 0u) && (pp[bx*KG] == mx);   // this block achieved the global max for k
  }
  __syncthreads();
  if (flag) atomicOr(&s_kbm[t >> 5], 1u << (t & 31));
  __syncthreads();
  if (any) {
    unsigned long long kbm = ((unsigned long long)s_kbm[1] << 32) | s_kbm[0];
    unsigned long long mask = rowm[r] & colm[g4] & kbm;
    while (mask) {
      int k = __ffsll(mask) - 1;
      mask &= mask - 1;
      float4 gb = sbox[k];
      float ga = sarea[k];
      float sv = sgm[k];
#pragma unroll
      for (int j = 0; j < 4; j++) {
        if (!ins[j]) continue;
        float ix = fmaxf(0.f, __fadd_rn(__fsub_rn(fminf(ax2[j], gb.z), fmaxf(ax1[j], gb.x)), 1.f));
        float iy = fmaxf(0.f, __fadd_rn(__fsub_rn(fminf(ay2[j], gb.w), fmaxf(ay1[j], gb.y)), 1.f));
        float inter = __fmul_rn(ix, iy);
        if (inter <= 0.f) continue;
        float den = __fsub_rn(__fadd_rn(aarea[j], ga), inter);
        isb[j] |= (__fdiv_rn(inter, den) == sv);   // bit-exact recompute vs pass 1
      }
    }
  }
  float4 vb4 = *reinterpret_cast<const float4*>(g_vb + b*NN + m0);
  float vb[4] = {vb4.x, vb4.y, vb4.z, vb4.w};
  float lblv[4];
#pragma unroll
  for (int j = 0; j < 4; j++) {
    float l = -1.f;
    if (ins[j]) {
      if (vb[j] < 0.3f)  l = 0.f;
      if (isb[j])        l = 1.f;
      if (vb[j] >= 0.7f) l = 1.f;
    }
    lblv[j] = l;
  }
  *reinterpret_cast<float4*>(g_lbl + b*NN + m0) =
      make_float4(lblv[0], lblv[1], lblv[2], lblv[3]);
  int lane = t & 31;
  unsigned kf0 = keys.k[b][0], kf1 = keys.k[b][1];
  unsigned kb0 = keys.k[b][2], kb1 = keys.k[b][3];
#pragma unroll
  for (int j = 0; j < 4; j++) {
    unsigned s = (unsigned)(s0 + j);
    unsigned n = s * AA + (unsigned)a;
    unsigned m = (unsigned)(m0 + j);
    emit_cand(lblv[j] == 1.f, b, 0, kf0, kf1, n, m, lane);
    emit_cand(lblv[j] == 0.f, b, 1, kb0, kb1, n, m, lane);
  }
}

// keep top `limit` candidates by (rng desc, n asc); disable rest.
// histogram prebuilt in g_hist; scan reads it directly (int4, aligned).
__device__ void select_top(float* __restrict__ lbl, const int2* __restrict__ list,
                           const int* __restrict__ gh,
                           int cnt, int limit,
                           unsigned* tie_v, unsigned* tie_p,
                           int* wsum, int* s_sel, int t) {
  if (t == 0) s_sel[2] = 0;
  int base = 4095 - 4*t;
  int4 hh4 = *reinterpret_cast<const int4*>(gh + base - 3);
  int h0 = hh4.w, h1 = hh4.z, h2 = hh4.y, h3 = hh4.x;
  int local = h0 + h1 + h2 + h3;
  int lane = t & 31, wid = t >> 5;
  int x = local;
#pragma unroll
  for (int o = 1; o < 32; o <<= 1) {
    int y = __shfl_up_sync(0xffffffffu, x, o);
    if (lane >= o) x += y;
  }
  if (lane == 31) wsum[wid] = x;
  __syncthreads();
  if (wid == 0) {
    int s = wsum[lane];
#pragma unroll
    for (int o = 1; o < 32; o <<= 1) {
      int y = __shfl_up_sync(0xffffffffu, s, o);
      if (lane >= o) s += y;
    }
    wsum[lane] = s;
  }
  __syncthreads();
  int prefix = (wid ? wsum[wid-1] : 0) + (x - local);
  if (prefix < limit && prefix + local >= limit) {
    int p = prefix; int hh[4] = {h0, h1, h2, h3};
#pragma unroll
    for (int j = 0; j < 4; j++) {
      if (p + hh[j] >= limit) { s_sel[0] = base - j; s_sel[1] = limit - p; break; }
      p += hh[j];
    }
  }
  __syncthreads();
  int cb = s_sel[0], r = s_sel[1];
  for (int i = t; i < cnt; i += NT) {
    int2 e = list[i];
    unsigned v = (unsigned)e.y;
    unsigned pk = (unsigned)e.x;
    int bkt = (int)(v >> 11);
    if (bkt < cb) lbl[pk & 0xFFFFu] = -1.f;
    else if (bkt == cb) {
      int p = atomicAdd(&s_sel[2], 1);
      if (p < 1024) { tie_v[p] = v; tie_p[p] = pk; }
      else lbl[pk & 0xFFFFu] = -1.f;   // statistically unreachable
    }
  }
  __syncthreads();
  int mm = min(s_sel[2], 1024);
  for (int i = t; i < mm; i += NT) {
    unsigned vi = tie_v[i]; unsigned ni = tie_p[i] >> 16; int rank = 0;
    for (int j = 0; j < mm; j++) {
      unsigned vj = tie_v[j];
      if (vj > vi || (vj == vi && (tie_p[j] >> 16) < ni)) rank++;
    }
    if (rank >= r) lbl[tie_p[i] & 0xFFFFu] = -1.f;
  }
  __syncthreads();
}

// grid (BB, 2): blockIdx.y==0 -> fg select; ==1 -> bg select (+uw). Independent.
__global__ __launch_bounds__(NT) void subsample_kernel() {
  int b = blockIdx.x; int cat = blockIdx.y; int t = threadIdx.x;
  __shared__ unsigned tie_v[1024];
  __shared__ unsigned tie_p[1024];
  __shared__ int wsum[32];
  __shared__ int s_sel[3];
  cudaGridDependencySynchronize();
  cudaTriggerProgrammaticLaunchCompletion();
  float* lbl = g_lbl + b*NN;
  int fgc = g_cnt[b*2], bgc = g_cnt[b*2 + 1];
  int fg_kept = min(fgc, 128);
  if (cat == 0) {
    if (fgc > 128)
      select_top(lbl, g_cand + (b*2)*NN, g_hist + (b*2)*4096, fgc, 128,
                 tie_v, tie_p, wsum, s_sel, t);
  } else {
    int limit = 256 - fg_kept;
    if (bgc > limit)
      select_top(lbl, g_cand + (b*2 + 1)*NN, g_hist + (b*2 + 1)*4096, bgc, limit,
                 tie_v, tie_p, wsum, s_sel, t);
    if (t == 0) g_uw[b] = 1.f / (float)(fg_kept + min(bgc, limit));
  }
}

// scalar form (R9): 30 regs, high occupancy; geometry before grid-dep sync
__global__ void output_kernel(const float* __restrict__ gt,
                              const float* __restrict__ iminfo,
                              float* __restrict__ out) {
  int idx = blockIdx.x * 256 + threadIdx.x;      // exactly LBL_SZ threads
  int s = idx & (HWV - 1);
  int t12 = idx >> 12;
  int a = t12 % AA;
  int b = t12 / AA;
  float imh = iminfo[0], imw = iminfo[1];
  float fx = (float)((s & 63) * 16);
  float fy = (float)((s >> 6) * 16);
  float ax1 = c_anch[a][0] + fx, ay1 = c_anch[a][1] + fy;
  float ax2 = c_anch[a][2] + fx, ay2 = c_anch[a][3] + fy;
  bool inside = (ax1 >= 0.f) && (ay1 >= 0.f) && (ax2 < imw) && (ay2 < imh);
  float aw = ax2 - ax1 + 1.f, ah = ay2 - ay1 + 1.f;
  float acx = ax1 + 0.5f*(aw - 1.f), acy = ay1 + 0.5f*(ah - 1.f);
  cudaGridDependencySynchronize();
  float lbl = g_lbl[idx];                        // m-layout == output labels layout
  int arg = (int)g_arg[idx];
  const float* g = gt + (b*KG + arg)*5;
  float gw = g[2] - g[0] + 1.f, gh = g[3] - g[1] + 1.f;
  float gcx = g[0] + 0.5f*(gw - 1.f), gcy = g[1] + 0.5f*(gh - 1.f);
  float t0 = (gcx - acx) / aw;
  float t1 = (gcy - acy) / ah;
  float t2 = logf(gw / aw);
  float t3 = logf(gh / ah);
  float inw = (lbl == 1.f) ? 1.f : 0.f;
  float ow  = (lbl == 1.f || lbl == 0.f) ? g_uw[b] : 0.f;
  if (!inside) { t0 = t1 = t2 = t3 = 0.f; inw = 0.f; ow = 0.f; lbl = 0.f; }
  out[idx] = lbl;
  int cb = (b*36 + a*4)*HWV + s;
  float tv[4] = {t0, t1, t2, t3};
#pragma unroll
  for (int c4 = 0; c4 < 4; c4++) {
    out[LBL_SZ            + cb + c4*HWV] = tv[c4];
    out[LBL_SZ +   CH_SZ  + cb + c4*HWV] = inw;
    out[LBL_SZ + 2*CH_SZ  + cb + c4*HWV] = ow;
  }
}

// ---------------- host --------------------------------------------------------
extern "C" void kernel_launch(void* const* d_in, const int* in_sizes, int n_in,
                              void* d_out, int out_size) {
  const float* gt     = (const float*)d_in[1];   // (B,50,5)
  const float* iminfo = (const float*)d_in[2];   // (B,2), ref uses row 0
  float* out = (float*)d_out;

  Keys keys;
  for (int b = 0; b < BB; b++) {
#if JAX_PARTITIONABLE
    unsigned b0, b1; tf2x32(0u, 42u, 0u, (unsigned)b, b0, b1);
    unsigned f0, f1, g0, g1;
    tf2x32(b0, b1, 0u, 0u, f0, f1);
    tf2x32(b0, b1, 0u, 1u, g0, g1);
    keys.k[b][0] = f0; keys.k[b][1] = f1; keys.k[b][2] = g0; keys.k[b][3] = g1;
#else
    unsigned y0[16], y1[16], flat[32];
    for (int i = 0; i < 16; i++) tf2x32(0u, 42u, (unsigned)i, (unsigned)(i+16), y0[i], y1[i]);
    for (int i = 0; i < 16; i++) { flat[i] = y0[i]; flat[16+i] = y1[i]; }
    unsigned kb0 = flat[2*b], kb1 = flat[2*b+1];
    unsigned p00, p01, p10, p11;
    tf2x32(kb0, kb1, 0u, 2u, p00, p01);
    tf2x32(kb0, kb1, 1u, 3u, p10, p11);
    keys.k[b][0] = p00; keys.k[b][1] = p10;
    keys.k[b][2] = p01; keys.k[b][3] = p11;
#endif
  }

  cudaLaunchAttribute pdl[1];
  pdl[0].id = cudaLaunchAttributeProgrammaticStreamSerialization;
  pdl[0].val.programmaticStreamSerializationAllowed = 1;

  // main: no PDL attribute (first in chain)
  main_kernel<<<dim3(NBLK, BB), 128>>>(gt, iminfo);

  {
    cudaLaunchConfig_t cfg = {};
    cfg.gridDim = dim3(NBLK, BB); cfg.blockDim = dim3(128);
    cfg.attrs = pdl; cfg.numAttrs = 1;
    cudaLaunchKernelEx(&cfg, labels_kernel, gt, iminfo, keys);
  }
  {
    cudaLaunchConfig_t cfg = {};
    cfg.gridDim = dim3(BB, 2); cfg.blockDim = dim3(NT);
    cfg.attrs = pdl; cfg.numAttrs = 1;
    cudaLaunchKernelEx(&cfg, subsample_kernel);
  }
  {
    cudaLaunchConfig_t cfg = {};
    cfg.gridDim = dim3(LBL_SZ/256); cfg.blockDim = dim3(256);
    cfg.attrs = pdl; cfg.numAttrs = 1;
    cudaLaunchKernelEx(&cfg, output_kernel, gt, iminfo, out);
  }
}

// round 14
// speedup vs baseline: 1.3340x; 1.3340x over previous
#include <cuda_runtime.h>
#include <cstdint>

#define JAX_PARTITIONABLE 1

#define BB 16
#define KG 50
#define AA 9
#define HWV 4096
#define NN 36864                      // 9*4096
#define NBLK 36                       // main/labels blocks per batch
#define LBL_SZ (BB*AA*HWV)            // 589824
#define CH_SZ  (BB*36*HWV)            // 2359296
#define NT 1024

// ---------------- scratch -----------------------------------------------------
__device__ unsigned g_part[BB*NBLK*KG]; // per-block per-GT max (bits), overwritten each replay
__device__ float g_vb[BB*NN];           // per-anchor best IoU (rounded)
__device__ float g_lbl[BB*NN];          // indexed by m = a*4096 + s
__device__ unsigned char g_arg[BB*NN];
__device__ float g_uw[BB];
__device__ int  g_cnt[BB*2];            // fg/bg candidate counts (zeroed by main)
__device__ int  g_hist[BB*2*4096];      // rng-bucket histogram (zeroed by main, filled by labels)
__device__ int2 g_cand[BB*2*NN];        // .x = (n_orig<<16)|m, .y = rng23

__constant__ float c_anch[9][4] = {
  {-84.f,-40.f,99.f,55.f},
  {-176.f,-88.f,191.f,103.f},
  {-360.f,-184.f,375.f,199.f},
  {-56.f,-56.f,71.f,71.f},
  {-120.f,-120.f,135.f,135.f},
  {-248.f,-248.f,263.f,263.f},
  {-36.f,-80.f,51.f,95.f},
  {-80.f,-168.f,95.f,183.f},
  {-168.f,-344.f,183.f,359.f}
};

// ---------------- threefry-2x32 (20 rounds), matches JAX ----------------------
__host__ __device__ inline void tf2x32(unsigned k0, unsigned k1,
                                       unsigned x0, unsigned x1,
                                       unsigned &o0, unsigned &o1) {
  unsigned ks2 = k0 ^ k1 ^ 0x1BD11BDAu;
#define TF_R(r) { x0 += x1; x1 = (x1<<(r))|(x1>>(32-(r))); x1 ^= x0; }
  x0 += k0; x1 += k1;
  TF_R(13) TF_R(15) TF_R(26) TF_R(6)
  x0 += k1; x1 += ks2 + 1u;
  TF_R(17) TF_R(29) TF_R(16) TF_R(24)
  x0 += ks2; x1 += k0 + 2u;
  TF_R(13) TF_R(15) TF_R(26) TF_R(6)
  x0 += k0; x1 += k1 + 3u;
  TF_R(17) TF_R(29) TF_R(16) TF_R(24)
  x0 += k1; x1 += ks2 + 4u;
  TF_R(13) TF_R(15) TF_R(26) TF_R(6)
  x0 += ks2; x1 += k0 + 5u;
#undef TF_R
  o0 = x0; o1 = x1;
}

__device__ inline unsigned rng23(unsigned k0, unsigned k1, unsigned n) {
#if JAX_PARTITIONABLE
  unsigned o0, o1; tf2x32(k0, k1, 0u, n, o0, o1);
  return (o0 ^ o1) >> 9;
#else
  const unsigned half = NN/2;
  unsigned o0, o1;
  if (n < half) { tf2x32(k0, k1, n, n + half, o0, o1); return o0 >> 9; }
  tf2x32(k0, k1, n - half, n, o0, o1); return o1 >> 9;
#endif
}

struct Keys { unsigned k[BB][4]; };

// block->anchor mapping with row interleaving: block q=bx&3 owns rows q,q+4,...,q+60
// thread t: local_row lr=t>>4, colgroup cg=t&15; row = q+4*lr; s0 = row*64+cg*4.

// ---------------- kernels ------------------------------------------------------

// Pass 1: per-anchor argmax (vb, barg) + per-block per-GT watermark max.
__global__ __launch_bounds__(256) void main_kernel(const float* __restrict__ gt,
                                                   const float* __restrict__ iminfo) {
  int b = blockIdx.y, t = threadIdx.x;
  int bx = blockIdx.x;
  int a  = bx >> 2;
  int q  = bx & 3;
  int lr = t >> 4, cg = t & 15;
  int row = q + 4*lr;
  int s0 = row*64 + cg*4;
  int m0 = a*4096 + s0;
  __shared__ float4 sbox[KG];
  __shared__ float sarea[KG];
  __shared__ unsigned smax[KG];
  __shared__ unsigned long long rowm[16], colm[16];
  if (t < KG) {
    const float* g = gt + (b*KG + t)*5;
    float x1 = g[0], y1 = g[1], x2 = g[2], y2 = g[3];
    sbox[t] = make_float4(x1, y1, x2, y2);
    sarea[t] = __fmul_rn(__fadd_rn(__fsub_rn(x2, x1), 1.f),
                         __fadd_rn(__fsub_rn(y2, y1), 1.f));
    smax[t] = 0u;
  }
  if (bx == 0 && t < 2) g_cnt[b*2 + t] = 0;
  {   // zero rng histogram (consumed by subsample after labels fills it)
    int gid = (b*NBLK + bx)*256 + t;
    if (gid < BB*2*4096) g_hist[gid] = 0;
  }
  __syncthreads();
  float c0 = c_anch[a][0], c1 = c_anch[a][1], c2 = c_anch[a][2], c3 = c_anch[a][3];
  if (t < 16) {             // row band masks (y): entry t -> row q+4*t
    float y1r = c1 + (float)((q + 4*t) * 16);
    float y2r = c3 + (float)((q + 4*t) * 16);
    unsigned long long mm = 0ull;
    for (int k = 0; k < KG; k++) {
      float4 gb = sbox[k];
      if (!(gb.y - y2r >= 1.f || y1r - gb.w >= 1.f)) mm |= 1ull << k;
    }
    rowm[t] = mm;
  } else if (t < 32) {      // column-group band masks (x)
    int g4 = t - 16;
    float x1g = c0 + (float)((g4 * 4) * 16);
    float x2g = c2 + (float)((g4 * 4 + 3) * 16);
    unsigned long long mm = 0ull;
    for (int k = 0; k < KG; k++) {
      float4 gb = sbox[k];
      if (!(gb.x - x2g >= 1.f || x1g - gb.z >= 1.f)) mm |= 1ull << k;
    }
    colm[g4] = mm;
  }
  __syncthreads();
  float imh = iminfo[0], imw = iminfo[1];
  float ax1[4], ay1[4], ax2[4], ay2[4], aarea[4];
  bool ins[4]; bool any = false;
  float bi[4], bd[4]; int barg[4];
#pragma unroll
  for (int j = 0; j < 4; j++) {
    int s = s0 + j;
    float fx = (float)((s & 63) * 16);
    float fy = (float)((s >> 6) * 16);
    ax1[j] = __fadd_rn(c0, fx); ay1[j] = __fadd_rn(c1, fy);
    ax2[j] = __fadd_rn(c2, fx); ay2[j] = __fadd_rn(c3, fy);
    aarea[j] = __fmul_rn(__fadd_rn(__fsub_rn(ax2[j], ax1[j]), 1.f),
                         __fadd_rn(__fsub_rn(ay2[j], ay1[j]), 1.f));
    ins[j] = (ax1[j] >= 0.f) && (ay1[j] >= 0.f) && (ax2[j] < imw) && (ay2[j] < imh);
    any |= ins[j];
    bi[j] = 0.f; bd[j] = 1.f; barg[j] = 0;
  }
  if (any) {
    unsigned long long mask = rowm[lr] & colm[cg];
    while (mask) {
      int k = __ffsll(mask) - 1;
      mask &= mask - 1;
      float4 gb = sbox[k];
      float ga = sarea[k];
#pragma unroll
      for (int j = 0; j < 4; j++) {
        if (!ins[j]) continue;
        float ix = fmaxf(0.f, __fadd_rn(__fsub_rn(fminf(ax2[j], gb.z), fmaxf(ax1[j], gb.x)), 1.f));
        float iy = fmaxf(0.f, __fadd_rn(__fsub_rn(fminf(ay2[j], gb.w), fmaxf(ay1[j], gb.y)), 1.f));
        float inter = __fmul_rn(ix, iy);
        if (inter <= 0.f) continue;
        float den = __fsub_rn(__fadd_rn(aarea[j], ga), inter);
        // per-GT watermark max (inside anchors only)
        unsigned wmb = smax[k];
        float wm = __uint_as_float(wmb);
        if (__fmul_rn(inter, 1.000004f) >= __fmul_rn(wm, den)) {
          unsigned v = __float_as_uint(__fdiv_rn(inter, den));
          if (v > wmb) atomicMax(&smax[k], v);
        }
        // per-anchor argmax via fraction compare + exact fallback in window
        float L = __fmul_rn(inter, bd[j]), R = __fmul_rn(bi[j], den);
        if (L > __fmul_rn(R, 1.000004f)) { bi[j] = inter; bd[j] = den; barg[j] = k; }
        else if (__fmul_rn(L, 1.000004f) >= R) {
          if (__fdiv_rn(inter, den) > __fdiv_rn(bi[j], bd[j])) {
            bi[j] = inter; bd[j] = den; barg[j] = k;
          }
        }
      }
    }
  }
  __syncthreads();
  if (t < KG) g_part[(b*NBLK + bx)*KG + t] = smax[t];
  float vb[4];
#pragma unroll
  for (int j = 0; j < 4; j++)
    vb[j] = (bi[j] > 0.f) ? __fdiv_rn(bi[j], bd[j]) : 0.f;
  *reinterpret_cast<float4*>(g_vb + b*NN + m0) = make_float4(vb[0], vb[1], vb[2], vb[3]);
  *reinterpret_cast<uchar4*>(g_arg + b*NN + m0) =
      make_uchar4((unsigned char)barg[0], (unsigned char)barg[1],
                  (unsigned char)barg[2], (unsigned char)barg[3]);
}

__device__ __forceinline__ void emit_cand(bool pred, int b, int cat,
                                          unsigned kk0, unsigned kk1,
                                          unsigned n, unsigned m, int lane) {
  unsigned msk = __ballot_sync(0xffffffffu, pred);
  if (!msk) return;
  unsigned v = 0;
  if (pred) v = rng23(kk0, kk1, n);
  int leader = __ffs(msk) - 1;
  int base = 0;
  if (lane == leader) base = atomicAdd(&g_cnt[b*2 + cat], __popc(msk));
  base = __shfl_sync(0xffffffffu, base, leader);
  if (pred) {
    int pos = base + __popc(msk & ((1u << lane) - 1u));
    g_cand[(b*2 + cat)*NN + pos] = make_int2((int)((n << 16) | m), (int)v);
    atomicAdd(&g_hist[(b*2 + cat)*4096 + (v >> 11)], 1);   // histogram at emission
  }
}

// Pass 2 (light): labels from vb + tiny is_best check restricted to k's whose
// global max was achieved inside THIS block (kbm).
__global__ __launch_bounds__(256) void labels_kernel(const float* __restrict__ gt,
                                                     const float* __restrict__ iminfo,
                                                     Keys keys) {
  int b = blockIdx.y, t = threadIdx.x;
  int bx = blockIdx.x;
  int a  = bx >> 2;
  int q  = bx & 3;
  int lr = t >> 4, cg = t & 15;
  int row = q + 4*lr;
  int s0 = row*64 + cg*4;
  int m0 = a*4096 + s0;
  __shared__ float4 sbox[KG];
  __shared__ float sarea[KG];
  __shared__ float sgm[KG];
  __shared__ unsigned s_kbm[2];
  __shared__ unsigned long long rowm[16], colm[16];
  bool flag = false;
  if (t < KG) {
    const float* g = gt + (b*KG + t)*5;
    float x1 = g[0], y1 = g[1], x2 = g[2], y2 = g[3];
    sbox[t] = make_float4(x1, y1, x2, y2);
    sarea[t] = __fmul_rn(__fadd_rn(__fsub_rn(x2, x1), 1.f),
                         __fadd_rn(__fsub_rn(y2, y1), 1.f));
    unsigned mx = 0u;
    const unsigned* pp = g_part + b*NBLK*KG + t;
#pragma unroll 6
    for (int i = 0; i < NBLK; i++) mx = max(mx, pp[i*KG]);
    sgm[t] = __uint_as_float(mx);             // mx==0 handled by flag (no match possible)
    flag = (mx != 0u) && (pp[bx*KG] == mx);   // this block achieved the global max for k
  }
  if (t >= KG && t < KG+2) s_kbm[t - KG] = 0u;
  __syncthreads();
  if (flag) atomicOr(&s_kbm[t >> 5], 1u << (t & 31));
  float c0 = c_anch[a][0], c1 = c_anch[a][1], c2 = c_anch[a][2], c3 = c_anch[a][3];
  if (t < 16) {
    float y1r = c1 + (float)((q + 4*t) * 16);
    float y2r = c3 + (float)((q + 4*t) * 16);
    unsigned long long mm = 0ull;
    for (int k = 0; k < KG; k++) {
      float4 gb = sbox[k];
      if (!(gb.y - y2r >= 1.f || y1r - gb.w >= 1.f)) mm |= 1ull << k;
    }
    rowm[t] = mm;
  } else if (t < 32) {
    int g4 = t - 16;
    float x1g = c0 + (float)((g4 * 4) * 16);
    float x2g = c2 + (float)((g4 * 4 + 3) * 16);
    unsigned long long mm = 0ull;
    for (int k = 0; k < KG; k++) {
      float4 gb = sbox[k];
      if (!(gb.x - x2g >= 1.f || x1g - gb.z >= 1.f)) mm |= 1ull << k;
    }
    colm[g4] = mm;
  }
  __syncthreads();
  float imh = iminfo[0], imw = iminfo[1];
  float ax1[4], ay1[4], ax2[4], ay2[4], aarea[4];
  bool ins[4]; bool any = false; bool isb[4];
#pragma unroll
  for (int j = 0; j < 4; j++) {
    int s = s0 + j;
    float fx = (float)((s & 63) * 16);
    float fy = (float)((s >> 6) * 16);
    ax1[j] = __fadd_rn(c0, fx); ay1[j] = __fadd_rn(c1, fy);
    ax2[j] = __fadd_rn(c2, fx); ay2[j] = __fadd_rn(c3, fy);
    aarea[j] = __fmul_rn(__fadd_rn(__fsub_rn(ax2[j], ax1[j]), 1.f),
                         __fadd_rn(__fsub_rn(ay2[j], ay1[j]), 1.f));
    ins[j] = (ax1[j] >= 0.f) && (ay1[j] >= 0.f) && (ax2[j] < imw) && (ay2[j] < imh);
    any |= ins[j];
    isb[j] = false;
  }
  if (any) {
    unsigned long long kbm = ((unsigned long long)s_kbm[1] << 32) | s_kbm[0];
    unsigned long long mask = rowm[lr] & colm[cg] & kbm;
    while (mask) {
      int k = __ffsll(mask) - 1;
      mask &= mask - 1;
      float4 gb = sbox[k];
      float ga = sarea[k];
      float sv = sgm[k];
#pragma unroll
      for (int j = 0; j < 4; j++) {
        if (!ins[j]) continue;
        float ix = fmaxf(0.f, __fadd_rn(__fsub_rn(fminf(ax2[j], gb.z), fmaxf(ax1[j], gb.x)), 1.f));
        float iy = fmaxf(0.f, __fadd_rn(__fsub_rn(fminf(ay2[j], gb.w), fmaxf(ay1[j], gb.y)), 1.f));
        float inter = __fmul_rn(ix, iy);
        if (inter <= 0.f) continue;
        float den = __fsub_rn(__fadd_rn(aarea[j], ga), inter);
        isb[j] |= (__fdiv_rn(inter, den) == sv);   // bit-exact recompute vs pass 1
      }
    }
  }
  float4 vb4 = *reinterpret_cast<const float4*>(g_vb + b*NN + m0);
  float vb[4] = {vb4.x, vb4.y, vb4.z, vb4.w};
  float lblv[4];
#pragma unroll
  for (int j = 0; j < 4; j++) {
    float l = -1.f;
    if (ins[j]) {
      if (vb[j] < 0.3f)  l = 0.f;
      if (isb[j])        l = 1.f;
      if (vb[j] >= 0.7f) l = 1.f;
    }
    lblv[j] = l;
  }
  *reinterpret_cast<float4*>(g_lbl + b*NN + m0) =
      make_float4(lblv[0], lblv[1], lblv[2], lblv[3]);
  int lane = t & 31;
  unsigned kf0 = keys.k[b][0], kf1 = keys.k[b][1];
  unsigned kb0 = keys.k[b][2], kb1 = keys.k[b][3];
#pragma unroll
  for (int j = 0; j < 4; j++) {
    unsigned s = (unsigned)(s0 + j);
    unsigned n = s * AA + (unsigned)a;
    unsigned m = (unsigned)(m0 + j);
    emit_cand(lblv[j] == 1.f, b, 0, kf0, kf1, n, m, lane);
    emit_cand(lblv[j] == 0.f, b, 1, kb0, kb1, n, m, lane);
  }
}

// keep top `limit` candidates by (rng desc, n asc); disable rest.
// histogram prebuilt in g_hist; scan reads it directly (int4, aligned).
__device__ void select_top(float* __restrict__ lbl, const int2* __restrict__ list,
                           const int* __restrict__ gh,
                           int cnt, int limit,
                           unsigned* tie_v, unsigned* tie_p,
                           int* wsum, int* s_sel, int t) {
  if (t == 0) s_sel[2] = 0;
  int base = 4095 - 4*t;
  int4 hh4 = *reinterpret_cast<const int4*>(gh + base - 3);
  int h0 = hh4.w, h1 = hh4.z, h2 = hh4.y, h3 = hh4.x;
  int local = h0 + h1 + h2 + h3;
  int lane = t & 31, wid = t >> 5;
  int x = local;
#pragma unroll
  for (int o = 1; o < 32; o <<= 1) {
    int y = __shfl_up_sync(0xffffffffu, x, o);
    if (lane >= o) x += y;
  }
  if (lane == 31) wsum[wid] = x;
  __syncthreads();
  if (wid == 0) {
    int s = wsum[lane];
#pragma unroll
    for (int o = 1; o < 32; o <<= 1) {
      int y = __shfl_up_sync(0xffffffffu, s, o);
      if (lane >= o) s += y;
    }
    wsum[lane] = s;
  }
  __syncthreads();
  int prefix = (wid ? wsum[wid-1] : 0) + (x - local);
  if (prefix < limit && prefix + local >= limit) {
    int p = prefix; int hh[4] = {h0, h1, h2, h3};
#pragma unroll
    for (int j = 0; j < 4; j++) {
      if (p + hh[j] >= limit) { s_sel[0] = base - j; s_sel[1] = limit - p; break; }
      p += hh[j];
    }
  }
  __syncthreads();
  int cb = s_sel[0], r = s_sel[1];
  for (int i = t; i < cnt; i += NT) {
    int2 e = list[i];
    unsigned v = (unsigned)e.y;
    unsigned pk = (unsigned)e.x;
    int bkt = (int)(v >> 11);
    if (bkt < cb) lbl[pk & 0xFFFFu] = -1.f;
    else if (bkt == cb) {
      int p = atomicAdd(&s_sel[2], 1);
      if (p < 1024) { tie_v[p] = v; tie_p[p] = pk; }
      else lbl[pk & 0xFFFFu] = -1.f;   // statistically unreachable
    }
  }
  __syncthreads();
  int mm = min(s_sel[2], 1024);
  for (int i = t; i < mm; i += NT) {
    unsigned vi = tie_v[i]; unsigned ni = tie_p[i] >> 16; int rank = 0;
    for (int j = 0; j < mm; j++) {
      unsigned vj = tie_v[j];
      if (vj > vi || (vj == vi && (tie_p[j] >> 16) < ni)) rank++;
    }
    if (rank >= r) lbl[tie_p[i] & 0xFFFFu] = -1.f;
  }
  __syncthreads();
}

// grid (BB, 2): blockIdx.y==0 -> fg select; ==1 -> bg select (+uw). Independent.
__global__ __launch_bounds__(NT) void subsample_kernel() {
  int b = blockIdx.x; int cat = blockIdx.y; int t = threadIdx.x;
  __shared__ unsigned tie_v[1024];
  __shared__ unsigned tie_p[1024];
  __shared__ int wsum[32];
  __shared__ int s_sel[3];
  float* lbl = g_lbl + b*NN;
  int fgc = g_cnt[b*2], bgc = g_cnt[b*2 + 1];
  int fg_kept = min(fgc, 128);
  if (cat == 0) {
    if (fgc > 128)
      select_top(lbl, g_cand + (b*2)*NN, g_hist + (b*2)*4096, fgc, 128,
                 tie_v, tie_p, wsum, s_sel, t);
  } else {
    int limit = 256 - fg_kept;
    if (bgc > limit)
      select_top(lbl, g_cand + (b*2 + 1)*NN, g_hist + (b*2 + 1)*4096, bgc, limit,
                 tie_v, tie_p, wsum, s_sel, t);
    if (t == 0) g_uw[b] = 1.f / (float)(fg_kept + min(bgc, limit));
  }
}

// scalar form (R9): 30 regs, high occupancy
__global__ void output_kernel(const float* __restrict__ gt,
                              const float* __restrict__ iminfo,
                              float* __restrict__ out) {
  int idx = blockIdx.x * 256 + threadIdx.x;      // exactly LBL_SZ threads
  int s = idx & (HWV - 1);
  int t12 = idx >> 12;
  int a = t12 % AA;
  int b = t12 / AA;
  float imh = iminfo[0], imw = iminfo[1];
  float fx = (float)((s & 63) * 16);
  float fy = (float)((s >> 6) * 16);
  float ax1 = c_anch[a][0] + fx, ay1 = c_anch[a][1] + fy;
  float ax2 = c_anch[a][2] + fx, ay2 = c_anch[a][3] + fy;
  bool inside = (ax1 >= 0.f) && (ay1 >= 0.f) && (ax2 < imw) && (ay2 < imh);
  float lbl = g_lbl[idx];                        // m-layout == output labels layout
  int arg = (int)g_arg[idx];
  const float* g = gt + (b*KG + arg)*5;
  float aw = ax2 - ax1 + 1.f, ah = ay2 - ay1 + 1.f;
  float acx = ax1 + 0.5f*(aw - 1.f), acy = ay1 + 0.5f*(ah - 1.f);
  float gw = g[2] - g[0] + 1.f, gh = g[3] - g[1] + 1.f;
  float gcx = g[0] + 0.5f*(gw - 1.f), gcy = g[1] + 0.5f*(gh - 1.f);
  float t0 = (gcx - acx) / aw;
  float t1 = (gcy - acy) / ah;
  float t2 = logf(gw / aw);
  float t3 = logf(gh / ah);
  float inw = (lbl == 1.f) ? 1.f : 0.f;
  float ow  = (lbl == 1.f || lbl == 0.f) ? g_uw[b] : 0.f;
  if (!inside) { t0 = t1 = t2 = t3 = 0.f; inw = 0.f; ow = 0.f; lbl = 0.f; }
  out[idx] = lbl;
  int cb = (b*36 + a*4)*HWV + s;
  float tv[4] = {t0, t1, t2, t3};
#pragma unroll
  for (int c4 = 0; c4 < 4; c4++) {
    out[LBL_SZ            + cb + c4*HWV] = tv[c4];
    out[LBL_SZ +   CH_SZ  + cb + c4*HWV] = inw;
    out[LBL_SZ + 2*CH_SZ  + cb + c4*HWV] = ow;
  }
}

// ---------------- host --------------------------------------------------------
extern "C" void kernel_launch(void* const* d_in, const int* in_sizes, int n_in,
                              void* d_out, int out_size) {
  const float* gt     = (const float*)d_in[1];   // (B,50,5)
  const float* iminfo = (const float*)d_in[2];   // (B,2), ref uses row 0
  float* out = (float*)d_out;

  Keys keys;
  for (int b = 0; b < BB; b++) {
#if JAX_PARTITIONABLE
    unsigned b0, b1; tf2x32(0u, 42u, 0u, (unsigned)b, b0, b1);
    unsigned f0, f1, g0, g1;
    tf2x32(b0, b1, 0u, 0u, f0, f1);
    tf2x32(b0, b1, 0u, 1u, g0, g1);
    keys.k[b][0] = f0; keys.k[b][1] = f1; keys.k[b][2] = g0; keys.k[b][3] = g1;
#else
    unsigned y0[16], y1[16], flat[32];
    for (int i = 0; i < 16; i++) tf2x32(0u, 42u, (unsigned)i, (unsigned)(i+16), y0[i], y1[i]);
    for (int i = 0; i < 16; i++) { flat[i] = y0[i]; flat[16+i] = y1[i]; }
    unsigned kb0 = flat[2*b], kb1 = flat[2*b+1];
    unsigned p00, p01, p10, p11;
    tf2x32(kb0, kb1, 0u, 2u, p00, p01);
    tf2x32(kb0, kb1, 1u, 3u, p10, p11);
    keys.k[b][0] = p00; keys.k[b][1] = p10;
    keys.k[b][2] = p01; keys.k[b][3] = p11;
#endif
  }

  dim3 gA(NBLK, BB);
  main_kernel<<<gA, 256>>>(gt, iminfo);
  labels_kernel<<<gA, 256>>>(gt, iminfo, keys);
  subsample_kernel<<<dim3(BB, 2), NT>>>();
  output_kernel<<<LBL_SZ/256, 256>>>(gt, iminfo, out);
}

// round 15
// speedup vs baseline: 1.4044x; 1.0528x over previous
#include <cuda_runtime.h>
#include <cstdint>

#define JAX_PARTITIONABLE 1

#define BB 16
#define KG 50
#define AA 9
#define HWV 4096
#define NN 36864                      // 9*4096
#define NBLK 36                       // main/labels blocks per batch
#define LBL_SZ (BB*AA*HWV)            // 589824
#define CH_SZ  (BB*36*HWV)            // 2359296
#define NT 1024

// ---------------- scratch -----------------------------------------------------
__device__ unsigned g_part[BB*NBLK*KG]; // per-block per-GT max (bits), overwritten each replay
__device__ float g_vb[BB*NN];           // per-anchor best IoU (rounded)
__device__ float g_lbl[BB*NN];          // indexed by m = a*4096 + s
__device__ unsigned char g_arg[BB*NN];
__device__ float g_uw[BB];
__device__ int  g_cnt[BB*2];            // fg/bg candidate counts (zeroed by main)
__device__ int  g_hist[BB*2*4096];      // rng-bucket histogram (zeroed by main, filled by labels)
__device__ int2 g_cand[BB*2*NN];        // .x = (n_orig<<16)|m, .y = rng23

__constant__ float c_anch[9][4] = {
  {-84.f,-40.f,99.f,55.f},
  {-176.f,-88.f,191.f,103.f},
  {-360.f,-184.f,375.f,199.f},
  {-56.f,-56.f,71.f,71.f},
  {-120.f,-120.f,135.f,135.f},
  {-248.f,-248.f,263.f,263.f},
  {-36.f,-80.f,51.f,95.f},
  {-80.f,-168.f,95.f,183.f},
  {-168.f,-344.f,183.f,359.f}
};

// ---------------- threefry-2x32 (20 rounds), matches JAX ----------------------
__host__ __device__ inline void tf2x32(unsigned k0, unsigned k1,
                                       unsigned x0, unsigned x1,
                                       unsigned &o0, unsigned &o1) {
  unsigned ks2 = k0 ^ k1 ^ 0x1BD11BDAu;
#define TF_R(r) { x0 += x1; x1 = (x1<<(r))|(x1>>(32-(r))); x1 ^= x0; }
  x0 += k0; x1 += k1;
  TF_R(13) TF_R(15) TF_R(26) TF_R(6)
  x0 += k1; x1 += ks2 + 1u;
  TF_R(17) TF_R(29) TF_R(16) TF_R(24)
  x0 += ks2; x1 += k0 + 2u;
  TF_R(13) TF_R(15) TF_R(26) TF_R(6)
  x0 += k0; x1 += k1 + 3u;
  TF_R(17) TF_R(29) TF_R(16) TF_R(24)
  x0 += k1; x1 += ks2 + 4u;
  TF_R(13) TF_R(15) TF_R(26) TF_R(6)
  x0 += ks2; x1 += k0 + 5u;
#undef TF_R
  o0 = x0; o1 = x1;
}

__device__ inline unsigned rng23(unsigned k0, unsigned k1, unsigned n) {
#if JAX_PARTITIONABLE
  unsigned o0, o1; tf2x32(k0, k1, 0u, n, o0, o1);
  return (o0 ^ o1) >> 9;
#else
  const unsigned half = NN/2;
  unsigned o0, o1;
  if (n < half) { tf2x32(k0, k1, n, n + half, o0, o1); return o0 >> 9; }
  tf2x32(k0, k1, n - half, n, o0, o1); return o1 >> 9;
#endif
}

struct Keys { unsigned k[BB][4]; };

// ---------------- kernels ------------------------------------------------------

// Pass 1: per-anchor argmax (vb, barg) + per-block per-GT watermark max.
// A thread's 4 anchors share row & type: y-geometry is scalar, iy computed once/k.
__global__ __launch_bounds__(256) void main_kernel(const float* __restrict__ gt,
                                                   const float* __restrict__ iminfo) {
  int b = blockIdx.y, t = threadIdx.x;
  int bx = blockIdx.x;
  int m0 = (bx * 256 + t) * 4;
  int a  = (bx * 1024) >> 12;                 // block covers one anchor type
  int base_row = ((bx & 3) * 1024) >> 6;      // 16 rows per block
  __shared__ float4 sbox[KG];
  __shared__ float sarea[KG];
  __shared__ unsigned smax[KG];
  __shared__ unsigned long long rowm[16], colm[16];
  if (t < KG) {
    const float* g = gt + (b*KG + t)*5;
    float x1 = g[0], y1 = g[1], x2 = g[2], y2 = g[3];
    sbox[t] = make_float4(x1, y1, x2, y2);
    sarea[t] = __fmul_rn(__fadd_rn(__fsub_rn(x2, x1), 1.f),
                         __fadd_rn(__fsub_rn(y2, y1), 1.f));
    smax[t] = 0u;
  }
  if (bx == 0 && t < 2) g_cnt[b*2 + t] = 0;
  {   // zero rng histogram (consumed by subsample after labels fills it)
    int gid = (b*NBLK + bx)*256 + t;
    if (gid < BB*2*4096) g_hist[gid] = 0;
  }
  __syncthreads();
  float c0 = c_anch[a][0], c1 = c_anch[a][1], c2 = c_anch[a][2], c3 = c_anch[a][3];
  if (t < 16) {             // row band masks (y)
    float y1r = c1 + (float)((base_row + t) * 16);
    float y2r = c3 + (float)((base_row + t) * 16);
    unsigned long long mm = 0ull;
    for (int k = 0; k < KG; k++) {
      float4 gb = sbox[k];
      if (!(gb.y - y2r >= 1.f || y1r - gb.w >= 1.f)) mm |= 1ull << k;
    }
    rowm[t] = mm;
  } else if (t < 32) {      // column-group band masks (x)
    int g4 = t - 16;
    float x1g = c0 + (float)((g4 * 4) * 16);
    float x2g = c2 + (float)((g4 * 4 + 3) * 16);
    unsigned long long mm = 0ull;
    for (int k = 0; k < KG; k++) {
      float4 gb = sbox[k];
      if (!(gb.x - x2g >= 1.f || x1g - gb.z >= 1.f)) mm |= 1ull << k;
    }
    colm[g4] = mm;
  }
  __syncthreads();
  float imh = iminfo[0], imw = iminfo[1];
  int s0 = m0 & 4095;
  int r = (s0 >> 6) - base_row;
  int g4 = (s0 & 63) >> 2;
  // scalar y geometry (shared by all 4 anchors of this thread)
  float fy = (float)((s0 >> 6) * 16);
  float ay1 = __fadd_rn(c1, fy), ay2 = __fadd_rn(c3, fy);
  bool ay_ok = (ay1 >= 0.f) && (ay2 < imh);
  float aw = __fadd_rn(__fsub_rn(c2, c0), 1.f);
  float ah = __fadd_rn(__fsub_rn(ay2, ay1), 1.f);
  float aarea = __fmul_rn(aw, ah);
  float ax1[4], ax2[4];
  bool ins[4]; bool any = false;
  float bi[4], bd[4]; int barg[4];
#pragma unroll
  for (int j = 0; j < 4; j++) {
    int s = s0 + j;
    float fx = (float)((s & 63) * 16);
    ax1[j] = __fadd_rn(c0, fx); ax2[j] = __fadd_rn(c2, fx);
    ins[j] = ay_ok && (ax1[j] >= 0.f) && (ax2[j] < imw);
    any |= ins[j];
    bi[j] = 0.f; bd[j] = 1.f; barg[j] = 0;
  }
  if (any) {
    unsigned long long mask = rowm[r] & colm[g4];
    while (mask) {
      int k = __ffsll(mask) - 1;
      mask &= mask - 1;
      float4 gb = sbox[k];
      float iy = fmaxf(0.f, __fadd_rn(__fsub_rn(fminf(ay2, gb.w), fmaxf(ay1, gb.y)), 1.f));
      if (iy <= 0.f) continue;
      float ga = sarea[k];
#pragma unroll
      for (int j = 0; j < 4; j++) {
        if (!ins[j]) continue;
        float ix = fmaxf(0.f, __fadd_rn(__fsub_rn(fminf(ax2[j], gb.z), fmaxf(ax1[j], gb.x)), 1.f));
        float inter = __fmul_rn(ix, iy);
        if (inter <= 0.f) continue;
        float den = __fsub_rn(__fadd_rn(aarea, ga), inter);
        // per-GT watermark max (inside anchors only)
        unsigned wmb = smax[k];
        float wm = __uint_as_float(wmb);
        if (__fmul_rn(inter, 1.000004f) >= __fmul_rn(wm, den)) {
          unsigned v = __float_as_uint(__fdiv_rn(inter, den));
          if (v > wmb) atomicMax(&smax[k], v);
        }
        // per-anchor argmax via fraction compare + exact fallback in window
        float L = __fmul_rn(inter, bd[j]), R = __fmul_rn(bi[j], den);
        if (L > __fmul_rn(R, 1.000004f)) { bi[j] = inter; bd[j] = den; barg[j] = k; }
        else if (__fmul_rn(L, 1.000004f) >= R) {
          if (__fdiv_rn(inter, den) > __fdiv_rn(bi[j], bd[j])) {
            bi[j] = inter; bd[j] = den; barg[j] = k;
          }
        }
      }
    }
  }
  __syncthreads();
  if (t < KG) g_part[(b*NBLK + bx)*KG + t] = smax[t];
  float vb[4];
#pragma unroll
  for (int j = 0; j < 4; j++)
    vb[j] = (bi[j] > 0.f) ? __fdiv_rn(bi[j], bd[j]) : 0.f;
  *reinterpret_cast<float4*>(g_vb + b*NN + m0) = make_float4(vb[0], vb[1], vb[2], vb[3]);
  *reinterpret_cast<uchar4*>(g_arg + b*NN + m0) =
      make_uchar4((unsigned char)barg[0], (unsigned char)barg[1],
                  (unsigned char)barg[2], (unsigned char)barg[3]);
}

__device__ __forceinline__ void emit_cand(bool pred, int b, int cat,
                                          unsigned kk0, unsigned kk1,
                                          unsigned n, unsigned m, int lane) {
  unsigned msk = __ballot_sync(0xffffffffu, pred);
  if (!msk) return;
  unsigned v = 0;
  if (pred) v = rng23(kk0, kk1, n);
  int leader = __ffs(msk) - 1;
  int base = 0;
  if (lane == leader) base = atomicAdd(&g_cnt[b*2 + cat], __popc(msk));
  base = __shfl_sync(0xffffffffu, base, leader);
  if (pred) {
    int pos = base + __popc(msk & ((1u << lane) - 1u));
    g_cand[(b*2 + cat)*NN + pos] = make_int2((int)((n << 16) | m), (int)v);
    atomicAdd(&g_hist[(b*2 + cat)*4096 + (v >> 11)], 1);   // histogram at emission
  }
}

// Pass 2 (light): labels from vb + tiny is_best check restricted to k's whose
// global max was achieved inside THIS block (kbm).
__global__ __launch_bounds__(256) void labels_kernel(const float* __restrict__ gt,
                                                     const float* __restrict__ iminfo,
                                                     Keys keys) {
  int b = blockIdx.y, t = threadIdx.x;
  int bx = blockIdx.x;
  int m0 = (bx * 256 + t) * 4;
  int a  = (bx * 1024) >> 12;
  int base_row = ((bx & 3) * 1024) >> 6;
  __shared__ float4 sbox[KG];
  __shared__ float sarea[KG];
  __shared__ float sgm[KG];
  __shared__ unsigned s_kbm[2];
  __shared__ unsigned long long rowm[16], colm[16];
  bool flag = false;
  if (t < KG) {
    const float* g = gt + (b*KG + t)*5;
    float x1 = g[0], y1 = g[1], x2 = g[2], y2 = g[3];
    sbox[t] = make_float4(x1, y1, x2, y2);
    sarea[t] = __fmul_rn(__fadd_rn(__fsub_rn(x2, x1), 1.f),
                         __fadd_rn(__fsub_rn(y2, y1), 1.f));
    unsigned mx = 0u;
    const unsigned* pp = g_part + b*NBLK*KG + t;
#pragma unroll 6
    for (int i = 0; i < NBLK; i++) mx = max(mx, pp[i*KG]);
    sgm[t] = __uint_as_float(mx);             // mx==0 handled by flag (no match possible)
    flag = (mx != 0u) && (pp[bx*KG] == mx);   // this block achieved the global max for k
  }
  if (t >= KG && t < KG+2) s_kbm[t - KG] = 0u;
  __syncthreads();
  if (flag) atomicOr(&s_kbm[t >> 5], 1u << (t & 31));
  float c0 = c_anch[a][0], c1 = c_anch[a][1], c2 = c_anch[a][2], c3 = c_anch[a][3];
  if (t < 16) {
    float y1r = c1 + (float)((base_row + t) * 16);
    float y2r = c3 + (float)((base_row + t) * 16);
    unsigned long long mm = 0ull;
    for (int k = 0; k < KG; k++) {
      float4 gb = sbox[k];
      if (!(gb.y - y2r >= 1.f || y1r - gb.w >= 1.f)) mm |= 1ull << k;
    }
    rowm[t] = mm;
  } else if (t < 32) {
    int g4 = t - 16;
    float x1g = c0 + (float)((g4 * 4) * 16);
    float x2g = c2 + (float)((g4 * 4 + 3) * 16);
    unsigned long long mm = 0ull;
    for (int k = 0; k < KG; k++) {
      float4 gb = sbox[k];
      if (!(gb.x - x2g >= 1.f || x1g - gb.z >= 1.f)) mm |= 1ull << k;
    }
    colm[g4] = mm;
  }
  __syncthreads();
  float imh = iminfo[0], imw = iminfo[1];
  int s0 = m0 & 4095;
  int r = (s0 >> 6) - base_row;
  int g4 = (s0 & 63) >> 2;
  float fy = (float)((s0 >> 6) * 16);
  float ay1 = __fadd_rn(c1, fy), ay2 = __fadd_rn(c3, fy);
  bool ay_ok = (ay1 >= 0.f) && (ay2 < imh);
  float aw = __fadd_rn(__fsub_rn(c2, c0), 1.f);
  float ah = __fadd_rn(__fsub_rn(ay2, ay1), 1.f);
  float aarea = __fmul_rn(aw, ah);
  float ax1[4], ax2[4];
  bool ins[4]; bool any = false; bool isb[4];
#pragma unroll
  for (int j = 0; j < 4; j++) {
    int s = s0 + j;
    float fx = (float)((s & 63) * 16);
    ax1[j] = __fadd_rn(c0, fx); ax2[j] = __fadd_rn(c2, fx);
    ins[j] = ay_ok && (ax1[j] >= 0.f) && (ax2[j] < imw);
    any |= ins[j];
    isb[j] = false;
  }
  if (any) {
    unsigned long long kbm = ((unsigned long long)s_kbm[1] << 32) | s_kbm[0];
    unsigned long long mask = rowm[r] & colm[g4] & kbm;
    while (mask) {
      int k = __ffsll(mask) - 1;
      mask &= mask - 1;
      float4 gb = sbox[k];
      float iy = fmaxf(0.f, __fadd_rn(__fsub_rn(fminf(ay2, gb.w), fmaxf(ay1, gb.y)), 1.f));
      if (iy <= 0.f) continue;
      float ga = sarea[k];
      float sv = sgm[k];
#pragma unroll
      for (int j = 0; j < 4; j++) {
        if (!ins[j]) continue;
        float ix = fmaxf(0.f, __fadd_rn(__fsub_rn(fminf(ax2[j], gb.z), fmaxf(ax1[j], gb.x)), 1.f));
        float inter = __fmul_rn(ix, iy);
        if (inter <= 0.f) continue;
        float den = __fsub_rn(__fadd_rn(aarea, ga), inter);
        isb[j] |= (__fdiv_rn(inter, den) == sv);   // bit-exact recompute vs pass 1
      }
    }
  }
  float4 vb4 = *reinterpret_cast<const float4*>(g_vb + b*NN + m0);
  float vb[4] = {vb4.x, vb4.y, vb4.z, vb4.w};
  float lblv[4];
#pragma unroll
  for (int j = 0; j < 4; j++) {
    float l = -1.f;
    if (ins[j]) {
      if (vb[j] < 0.3f)  l = 0.f;
      if (isb[j])        l = 1.f;
      if (vb[j] >= 0.7f) l = 1.f;
    }
    lblv[j] = l;
  }
  *reinterpret_cast<float4*>(g_lbl + b*NN + m0) =
      make_float4(lblv[0], lblv[1], lblv[2], lblv[3]);
  int lane = t & 31;
  unsigned kf0 = keys.k[b][0], kf1 = keys.k[b][1];
  unsigned kb0 = keys.k[b][2], kb1 = keys.k[b][3];
#pragma unroll
  for (int j = 0; j < 4; j++) {
    unsigned s = (unsigned)(s0 + j);
    unsigned n = s * AA + (unsigned)a;
    unsigned m = (unsigned)(m0 + j);
    emit_cand(lblv[j] == 1.f, b, 0, kf0, kf1, n, m, lane);
    emit_cand(lblv[j] == 0.f, b, 1, kb0, kb1, n, m, lane);
  }
}

// keep top `limit` candidates by (rng desc, n asc); disable rest.
// histogram prebuilt in g_hist; scan reads it directly (int4, aligned).
__device__ void select_top(float* __restrict__ lbl, const int2* __restrict__ list,
                           const int* __restrict__ gh,
                           int cnt, int limit,
                           unsigned* tie_v, unsigned* tie_p,
                           int* wsum, int* s_sel, int t) {
  if (t == 0) s_sel[2] = 0;
  int base = 4095 - 4*t;
  int4 hh4 = *reinterpret_cast<const int4*>(gh + base - 3);
  int h0 = hh4.w, h1 = hh4.z, h2 = hh4.y, h3 = hh4.x;
  int local = h0 + h1 + h2 + h3;
  int lane = t & 31, wid = t >> 5;
  int x = local;
#pragma unroll
  for (int o = 1; o < 32; o <<= 1) {
    int y = __shfl_up_sync(0xffffffffu, x, o);
    if (lane >= o) x += y;
  }
  if (lane == 31) wsum[wid] = x;
  __syncthreads();
  if (wid == 0) {
    int s = wsum[lane];
#pragma unroll
    for (int o = 1; o < 32; o <<= 1) {
      int y = __shfl_up_sync(0xffffffffu, s, o);
      if (lane >= o) s += y;
    }
    wsum[lane] = s;
  }
  __syncthreads();
  int prefix = (wid ? wsum[wid-1] : 0) + (x - local);
  if (prefix < limit && prefix + local >= limit) {
    int p = prefix; int hh[4] = {h0, h1, h2, h3};
#pragma unroll
    for (int j = 0; j < 4; j++) {
      if (p + hh[j] >= limit) { s_sel[0] = base - j; s_sel[1] = limit - p; break; }
      p += hh[j];
    }
  }
  __syncthreads();
  int cb = s_sel[0], r = s_sel[1];
  for (int i = t; i < cnt; i += NT) {
    int2 e = list[i];
    unsigned v = (unsigned)e.y;
    unsigned pk = (unsigned)e.x;
    int bkt = (int)(v >> 11);
    if (bkt < cb) lbl[pk & 0xFFFFu] = -1.f;
    else if (bkt == cb) {
      int p = atomicAdd(&s_sel[2], 1);
      if (p < 1024) { tie_v[p] = v; tie_p[p] = pk; }
      else lbl[pk & 0xFFFFu] = -1.f;   // statistically unreachable
    }
  }
  __syncthreads();
  int mm = min(s_sel[2], 1024);
  for (int i = t; i < mm; i += NT) {
    unsigned vi = tie_v[i]; unsigned ni = tie_p[i] >> 16; int rank = 0;
    for (int j = 0; j < mm; j++) {
      unsigned vj = tie_v[j];
      if (vj > vi || (vj == vi && (tie_p[j] >> 16) < ni)) rank++;
    }
    if (rank >= r) lbl[tie_p[i] & 0xFFFFu] = -1.f;
  }
  __syncthreads();
}

// grid (BB, 2): blockIdx.y==0 -> fg select; ==1 -> bg select (+uw). Independent.
__global__ __launch_bounds__(NT) void subsample_kernel() {
  int b = blockIdx.x; int cat = blockIdx.y; int t = threadIdx.x;
  __shared__ unsigned tie_v[1024];
  __shared__ unsigned tie_p[1024];
  __shared__ int wsum[32];
  __shared__ int s_sel[3];
  float* lbl = g_lbl + b*NN;
  int fgc = g_cnt[b*2], bgc = g_cnt[b*2 + 1];
  int fg_kept = min(fgc, 128);
  if (cat == 0) {
    if (fgc > 128)
      select_top(lbl, g_cand + (b*2)*NN, g_hist + (b*2)*4096, fgc, 128,
                 tie_v, tie_p, wsum, s_sel, t);
  } else {
    int limit = 256 - fg_kept;
    if (bgc > limit)
      select_top(lbl, g_cand + (b*2 + 1)*NN, g_hist + (b*2 + 1)*4096, bgc, limit,
                 tie_v, tie_p, wsum, s_sel, t);
    if (t == 0) g_uw[b] = 1.f / (float)(fg_kept + min(bgc, limit));
  }
}

// scalar form (R9): 30 regs, high occupancy
__global__ void output_kernel(const float* __restrict__ gt,
                              const float* __restrict__ iminfo,
                              float* __restrict__ out) {
  int idx = blockIdx.x * 256 + threadIdx.x;      // exactly LBL_SZ threads
  int s = idx & (HWV - 1);
  int t12 = idx >> 12;
  int a = t12 % AA;
  int b = t12 / AA;
  float imh = iminfo[0], imw = iminfo[1];
  float fx = (float)((s & 63) * 16);
  float fy = (float)((s >> 6) * 16);
  float ax1 = c_anch[a][0] + fx, ay1 = c_anch[a][1] + fy;
  float ax2 = c_anch[a][2] + fx, ay2 = c_anch[a][3] + fy;
  bool inside = (ax1 >= 0.f) && (ay1 >= 0.f) && (ax2 < imw) && (ay2 < imh);
  float lbl = g_lbl[idx];                        // m-layout == output labels layout
  int arg = (int)g_arg[idx];
  const float* g = gt + (b*KG + arg)*5;
  float aw = ax2 - ax1 + 1.f, ah = ay2 - ay1 + 1.f;
  float acx = ax1 + 0.5f*(aw - 1.f), acy = ay1 + 0.5f*(ah - 1.f);
  float gw = g[2] - g[0] + 1.f, gh = g[3] - g[1] + 1.f;
  float gcx = g[0] + 0.5f*(gw - 1.f), gcy = g[1] + 0.5f*(gh - 1.f);
  float t0 = (gcx - acx) / aw;
  float t1 = (gcy - acy) / ah;
  float t2 = logf(gw / aw);
  float t3 = logf(gh / ah);
  float inw = (lbl == 1.f) ? 1.f : 0.f;
  float ow  = (lbl == 1.f || lbl == 0.f) ? g_uw[b] : 0.f;
  if (!inside) { t0 = t1 = t2 = t3 = 0.f; inw = 0.f; ow = 0.f; lbl = 0.f; }
  out[idx] = lbl;
  int cb = (b*36 + a*4)*HWV + s;
  float tv[4] = {t0, t1, t2, t3};
#pragma unroll
  for (int c4 = 0; c4 < 4; c4++) {
    out[LBL_SZ            + cb + c4*HWV] = tv[c4];
    out[LBL_SZ +   CH_SZ  + cb + c4*HWV] = inw;
    out[LBL_SZ + 2*CH_SZ  + cb + c4*HWV] = ow;
  }
}

// ---------------- host --------------------------------------------------------
extern "C" void kernel_launch(void* const* d_in, const int* in_sizes, int n_in,
                              void* d_out, int out_size) {
  const float* gt     = (const float*)d_in[1];   // (B,50,5)
  const float* iminfo = (const float*)d_in[2];   // (B,2), ref uses row 0
  float* out = (float*)d_out;

  Keys keys;
  for (int b = 0; b < BB; b++) {
#if JAX_PARTITIONABLE
    unsigned b0, b1; tf2x32(0u, 42u, 0u, (unsigned)b, b0, b1);
    unsigned f0, f1, g0, g1;
    tf2x32(b0, b1, 0u, 0u, f0, f1);
    tf2x32(b0, b1, 0u, 1u, g0, g1);
    keys.k[b][0] = f0; keys.k[b][1] = f1; keys.k[b][2] = g0; keys.k[b][3] = g1;
#else
    unsigned y0[16], y1[16], flat[32];
    for (int i = 0; i < 16; i++) tf2x32(0u, 42u, (unsigned)i, (unsigned)(i+16), y0[i], y1[i]);
    for (int i = 0; i < 16; i++) { flat[i] = y0[i]; flat[16+i] = y1[i]; }
    unsigned kb0 = flat[2*b], kb1 = flat[2*b+1];
    unsigned p00, p01, p10, p11;
    tf2x32(kb0, kb1, 0u, 2u, p00, p01);
    tf2x32(kb0, kb1, 1u, 3u, p10, p11);
    keys.k[b][0] = p00; keys.k[b][1] = p10;
    keys.k[b][2] = p01; keys.k[b][3] = p11;
#endif
  }

  dim3 gA(NBLK, BB);
  main_kernel<<<gA, 256>>>(gt, iminfo);
  labels_kernel<<<gA, 256>>>(gt, iminfo, keys);
  subsample_kernel<<<dim3(BB, 2), NT>>>();
  output_kernel<<<LBL_SZ/256, 256>>>(gt, iminfo, out);
}

// round 16
// speedup vs baseline: 1.4351x; 1.0218x over previous
#include <cuda_runtime.h>
#include <cstdint>

#define JAX_PARTITIONABLE 1

#define BB 16
#define KG 50
#define AA 9
#define HWV 4096
#define NN 36864                      // 9*4096
#define NBLK 36                       // fused blocks per batch
#define NBLOCKS (BB*NBLK)             // 576 total (<= 148 SM * 4 resident)
#define LBL_SZ (BB*AA*HWV)            // 589824
#define CH_SZ  (BB*36*HWV)            // 2359296
#define NT 1024

// ---------------- scratch -----------------------------------------------------
__device__ unsigned g_part[BB*NBLK*KG]; // per-block per-GT max (bits)
__device__ float g_lbl[BB*NN];          // indexed by m = a*4096 + s
__device__ unsigned char g_arg[BB*NN];
__device__ float g_uw[BB];
__device__ int  g_cnt[BB*2];            // fg/bg candidate counts (zeroed in phase 1)
__device__ int  g_hist[BB*2*4096];      // rng-bucket histogram
__device__ int2 g_cand[BB*2*NN];        // .x = (n_orig<<16)|m, .y = rng23
__device__ unsigned g_barcnt = 0;       // grid barrier arrival counter
__device__ unsigned g_bargen = 0;       // grid barrier generation

__constant__ float c_anch[9][4] = {
  {-84.f,-40.f,99.f,55.f},
  {-176.f,-88.f,191.f,103.f},
  {-360.f,-184.f,375.f,199.f},
  {-56.f,-56.f,71.f,71.f},
  {-120.f,-120.f,135.f,135.f},
  {-248.f,-248.f,263.f,263.f},
  {-36.f,-80.f,51.f,95.f},
  {-80.f,-168.f,95.f,183.f},
  {-168.f,-344.f,183.f,359.f}
};

// ---------------- threefry-2x32 (20 rounds), matches JAX ----------------------
__host__ __device__ inline void tf2x32(unsigned k0, unsigned k1,
                                       unsigned x0, unsigned x1,
                                       unsigned &o0, unsigned &o1) {
  unsigned ks2 = k0 ^ k1 ^ 0x1BD11BDAu;
#define TF_R(r) { x0 += x1; x1 = (x1<<(r))|(x1>>(32-(r))); x1 ^= x0; }
  x0 += k0; x1 += k1;
  TF_R(13) TF_R(15) TF_R(26) TF_R(6)
  x0 += k1; x1 += ks2 + 1u;
  TF_R(17) TF_R(29) TF_R(16) TF_R(24)
  x0 += ks2; x1 += k0 + 2u;
  TF_R(13) TF_R(15) TF_R(26) TF_R(6)
  x0 += k0; x1 += k1 + 3u;
  TF_R(17) TF_R(29) TF_R(16) TF_R(24)
  x0 += k1; x1 += ks2 + 4u;
  TF_R(13) TF_R(15) TF_R(26) TF_R(6)
  x0 += ks2; x1 += k0 + 5u;
#undef TF_R
  o0 = x0; o1 = x1;
}

__device__ inline unsigned rng23(unsigned k0, unsigned k1, unsigned n) {
#if JAX_PARTITIONABLE
  unsigned o0, o1; tf2x32(k0, k1, 0u, n, o0, o1);
  return (o0 ^ o1) >> 9;
#else
  const unsigned half = NN/2;
  unsigned o0, o1;
  if (n < half) { tf2x32(k0, k1, n, n + half, o0, o1); return o0 >> 9; }
  tf2x32(k0, k1, n - half, n, o0, o1); return o1 >> 9;
#endif
}

struct Keys { unsigned k[BB][4]; };

// grid-wide barrier: safe because __launch_bounds__(256,4) guarantees all
// NBLOCKS=576 <= 148*4=592 blocks are co-resident.
__device__ __forceinline__ void grid_sync() {
  __syncthreads();
  if (threadIdx.x == 0) {
    unsigned my = g_bargen;           // stable: nobody bumps gen until all arrive
    __threadfence();
    unsigned v = atomicAdd(&g_barcnt, 1u);
    if (v == NBLOCKS - 1u) {
      g_barcnt = 0u;
      __threadfence();
      atomicExch(&g_bargen, my + 1u);
    } else {
      while (atomicAdd(&g_bargen, 0u) == my) { }
      __threadfence();
    }
  }
  __syncthreads();
}

__device__ __forceinline__ void emit_cand(bool pred, int b, int cat,
                                          unsigned kk0, unsigned kk1,
                                          unsigned n, unsigned m, int lane) {
  unsigned msk = __ballot_sync(0xffffffffu, pred);
  if (!msk) return;
  unsigned v = 0;
  if (pred) v = rng23(kk0, kk1, n);
  int leader = __ffs(msk) - 1;
  int base = 0;
  if (lane == leader) base = atomicAdd(&g_cnt[b*2 + cat], __popc(msk));
  base = __shfl_sync(0xffffffffu, base, leader);
  if (pred) {
    int pos = base + __popc(msk & ((1u << lane) - 1u));
    g_cand[(b*2 + cat)*NN + pos] = make_int2((int)((n << 16) | m), (int)v);
    atomicAdd(&g_hist[(b*2 + cat)*4096 + (v >> 11)], 1);
  }
}

// ---------------- fused main+labels ------------------------------------------
// Phase 1: per-anchor argmax + per-block per-GT watermark max (-> g_part).
// grid_sync. Phase 2: labels via kbm (own smax vs global max), reusing ALL
// smem tables and register state. No g_vb round trip, no duplicated setup.
__global__ __launch_bounds__(256, 4) void fused_kernel(const float* __restrict__ gt,
                                                       const float* __restrict__ iminfo,
                                                       Keys keys) {
  int b = blockIdx.y, t = threadIdx.x;
  int bx = blockIdx.x;
  int m0 = (bx * 256 + t) * 4;
  int a  = (bx * 1024) >> 12;                 // block covers one anchor type
  int base_row = ((bx & 3) * 1024) >> 6;      // 16 rows per block
  __shared__ float4 sbox[KG];
  __shared__ float sarea[KG];
  __shared__ unsigned smax[KG];
  __shared__ float sgm[KG];
  __shared__ unsigned s_kbm[2];
  __shared__ unsigned long long rowm[16], colm[16];
  if (t < KG) {
    const float* g = gt + (b*KG + t)*5;
    float x1 = g[0], y1 = g[1], x2 = g[2], y2 = g[3];
    sbox[t] = make_float4(x1, y1, x2, y2);
    sarea[t] = __fmul_rn(__fadd_rn(__fsub_rn(x2, x1), 1.f),
                         __fadd_rn(__fsub_rn(y2, y1), 1.f));
    smax[t] = 0u;
  }
  if (t >= KG && t < KG+2) s_kbm[t - KG] = 0u;
  if (bx == 0 && t < 2) g_cnt[b*2 + t] = 0;
  {   // zero rng histogram (consumed by subsample after phase 2 fills it)
    int gid = (b*NBLK + bx)*256 + t;
    if (gid < BB*2*4096) g_hist[gid] = 0;
  }
  __syncthreads();
  float c0 = c_anch[a][0], c1 = c_anch[a][1], c2 = c_anch[a][2], c3 = c_anch[a][3];
  if (t < 16) {             // row band masks (y)
    float y1r = c1 + (float)((base_row + t) * 16);
    float y2r = c3 + (float)((base_row + t) * 16);
    unsigned long long mm = 0ull;
    for (int k = 0; k < KG; k++) {
      float4 gb = sbox[k];
      if (!(gb.y - y2r >= 1.f || y1r - gb.w >= 1.f)) mm |= 1ull << k;
    }
    rowm[t] = mm;
  } else if (t < 32) {      // column-group band masks (x)
    int g4 = t - 16;
    float x1g = c0 + (float)((g4 * 4) * 16);
    float x2g = c2 + (float)((g4 * 4 + 3) * 16);
    unsigned long long mm = 0ull;
    for (int k = 0; k < KG; k++) {
      float4 gb = sbox[k];
      if (!(gb.x - x2g >= 1.f || x1g - gb.z >= 1.f)) mm |= 1ull << k;
    }
    colm[g4] = mm;
  }
  __syncthreads();
  float imh = iminfo[0], imw = iminfo[1];
  int s0 = m0 & 4095;
  int r = (s0 >> 6) - base_row;
  int g4 = (s0 & 63) >> 2;
  // scalar y geometry (4 anchors share row & type)
  float fy = (float)((s0 >> 6) * 16);
  float ay1 = __fadd_rn(c1, fy), ay2 = __fadd_rn(c3, fy);
  bool ay_ok = (ay1 >= 0.f) && (ay2 < imh);
  float aw = __fadd_rn(__fsub_rn(c2, c0), 1.f);
  float ah = __fadd_rn(__fsub_rn(ay2, ay1), 1.f);
  float aarea = __fmul_rn(aw, ah);
  float ax1[4], ax2[4];
  bool ins[4]; bool any = false;
  float bi[4], bd[4]; int barg[4];
#pragma unroll
  for (int j = 0; j < 4; j++) {
    int s = s0 + j;
    float fx = (float)((s & 63) * 16);
    ax1[j] = __fadd_rn(c0, fx); ax2[j] = __fadd_rn(c2, fx);
    ins[j] = ay_ok && (ax1[j] >= 0.f) && (ax2[j] < imw);
    any |= ins[j];
    bi[j] = 0.f; bd[j] = 1.f; barg[j] = 0;
  }
  unsigned long long bmask = rowm[r] & colm[g4];
  if (any) {
    unsigned long long mask = bmask;
    while (mask) {
      int k = __ffsll(mask) - 1;
      mask &= mask - 1;
      float4 gb = sbox[k];
      float iy = fmaxf(0.f, __fadd_rn(__fsub_rn(fminf(ay2, gb.w), fmaxf(ay1, gb.y)), 1.f));
      if (iy <= 0.f) continue;
      float ga = sarea[k];
#pragma unroll
      for (int j = 0; j < 4; j++) {
        if (!ins[j]) continue;
        float ix = fmaxf(0.f, __fadd_rn(__fsub_rn(fminf(ax2[j], gb.z), fmaxf(ax1[j], gb.x)), 1.f));
        float inter = __fmul_rn(ix, iy);
        if (inter <= 0.f) continue;
        float den = __fsub_rn(__fadd_rn(aarea, ga), inter);
        // per-GT watermark max (inside anchors only)
        unsigned wmb = smax[k];
        float wm = __uint_as_float(wmb);
        if (__fmul_rn(inter, 1.000004f) >= __fmul_rn(wm, den)) {
          unsigned v = __float_as_uint(__fdiv_rn(inter, den));
          if (v > wmb) atomicMax(&smax[k], v);
        }
        // per-anchor argmax via fraction compare + exact fallback in window
        float L = __fmul_rn(inter, bd[j]), R = __fmul_rn(bi[j], den);
        if (L > __fmul_rn(R, 1.000004f)) { bi[j] = inter; bd[j] = den; barg[j] = k; }
        else if (__fmul_rn(L, 1.000004f) >= R) {
          if (__fdiv_rn(inter, den) > __fdiv_rn(bi[j], bd[j])) {
            bi[j] = inter; bd[j] = den; barg[j] = k;
          }
        }
      }
    }
  }
  __syncthreads();
  if (t < KG) g_part[(b*NBLK + bx)*KG + t] = smax[t];
  *reinterpret_cast<uchar4*>(g_arg + b*NN + m0) =
      make_uchar4((unsigned char)barg[0], (unsigned char)barg[1],
                  (unsigned char)barg[2], (unsigned char)barg[3]);

  // ================== all blocks done with phase 1 ==================
  grid_sync();

  // ---- Phase 2: labels (smem tables + register state still live) ----
  bool flag = false;
  if (t < KG) {
    unsigned mx = 0u;
    const unsigned* pp = g_part + b*NBLK*KG + t;
#pragma unroll 6
    for (int i = 0; i < NBLK; i++) mx = max(mx, pp[i*KG]);
    sgm[t] = __uint_as_float(mx);             // mx==0 handled by flag
    flag = (mx != 0u) && (smax[t] == mx);     // this block achieved the global max
  }
  __syncthreads();
  if (flag) atomicOr(&s_kbm[t >> 5], 1u << (t & 31));
  __syncthreads();
  bool isb[4] = {false, false, false, false};
  if (any) {
    unsigned long long kbm = ((unsigned long long)s_kbm[1] << 32) | s_kbm[0];
    unsigned long long mask = bmask & kbm;
    while (mask) {
      int k = __ffsll(mask) - 1;
      mask &= mask - 1;
      float4 gb = sbox[k];
      float iy = fmaxf(0.f, __fadd_rn(__fsub_rn(fminf(ay2, gb.w), fmaxf(ay1, gb.y)), 1.f));
      if (iy <= 0.f) continue;
      float ga = sarea[k];
      float sv = sgm[k];
#pragma unroll
      for (int j = 0; j < 4; j++) {
        if (!ins[j]) continue;
        float ix = fmaxf(0.f, __fadd_rn(__fsub_rn(fminf(ax2[j], gb.z), fmaxf(ax1[j], gb.x)), 1.f));
        float inter = __fmul_rn(ix, iy);
        if (inter <= 0.f) continue;
        float den = __fsub_rn(__fadd_rn(aarea, ga), inter);
        isb[j] |= (__fdiv_rn(inter, den) == sv);   // bit-exact vs phase 1
      }
    }
  }
  float lblv[4];
#pragma unroll
  for (int j = 0; j < 4; j++) {
    float vb = (bi[j] > 0.f) ? __fdiv_rn(bi[j], bd[j]) : 0.f;
    float l = -1.f;
    if (ins[j]) {
      if (vb < 0.3f)  l = 0.f;
      if (isb[j])     l = 1.f;
      if (vb >= 0.7f) l = 1.f;
    }
    lblv[j] = l;
  }
  *reinterpret_cast<float4*>(g_lbl + b*NN + m0) =
      make_float4(lblv[0], lblv[1], lblv[2], lblv[3]);
  int lane = t & 31;
  unsigned kf0 = keys.k[b][0], kf1 = keys.k[b][1];
  unsigned kb0 = keys.k[b][2], kb1 = keys.k[b][3];
#pragma unroll
  for (int j = 0; j < 4; j++) {
    unsigned s = (unsigned)(s0 + j);
    unsigned n = s * AA + (unsigned)a;
    unsigned m = (unsigned)(m0 + j);
    emit_cand(lblv[j] == 1.f, b, 0, kf0, kf1, n, m, lane);
    emit_cand(lblv[j] == 0.f, b, 1, kb0, kb1, n, m, lane);
  }
}

// keep top `limit` candidates by (rng desc, n asc); disable rest.
__device__ void select_top(float* __restrict__ lbl, const int2* __restrict__ list,
                           const int* __restrict__ gh,
                           int cnt, int limit,
                           unsigned* tie_v, unsigned* tie_p,
                           int* wsum, int* s_sel, int t) {
  if (t == 0) s_sel[2] = 0;
  int base = 4095 - 4*t;
  int4 hh4 = *reinterpret_cast<const int4*>(gh + base - 3);
  int h0 = hh4.w, h1 = hh4.z, h2 = hh4.y, h3 = hh4.x;
  int local = h0 + h1 + h2 + h3;
  int lane = t & 31, wid = t >> 5;
  int x = local;
#pragma unroll
  for (int o = 1; o < 32; o <<= 1) {
    int y = __shfl_up_sync(0xffffffffu, x, o);
    if (lane >= o) x += y;
  }
  if (lane == 31) wsum[wid] = x;
  __syncthreads();
  if (wid == 0) {
    int s = wsum[lane];
#pragma unroll
    for (int o = 1; o < 32; o <<= 1) {
      int y = __shfl_up_sync(0xffffffffu, s, o);
      if (lane >= o) s += y;
    }
    wsum[lane] = s;
  }
  __syncthreads();
  int prefix = (wid ? wsum[wid-1] : 0) + (x - local);
  if (prefix < limit && prefix + local >= limit) {
    int p = prefix; int hh[4] = {h0, h1, h2, h3};
#pragma unroll
    for (int j = 0; j < 4; j++) {
      if (p + hh[j] >= limit) { s_sel[0] = base - j; s_sel[1] = limit - p; break; }
      p += hh[j];
    }
  }
  __syncthreads();
  int cb = s_sel[0], r = s_sel[1];
  for (int i = t; i < cnt; i += NT) {
    int2 e = list[i];
    unsigned v = (unsigned)e.y;
    unsigned pk = (unsigned)e.x;
    int bkt = (int)(v >> 11);
    if (bkt < cb) lbl[pk & 0xFFFFu] = -1.f;
    else if (bkt == cb) {
      int p = atomicAdd(&s_sel[2], 1);
      if (p < 1024) { tie_v[p] = v; tie_p[p] = pk; }
      else lbl[pk & 0xFFFFu] = -1.f;   // statistically unreachable
    }
  }
  __syncthreads();
  int mm = min(s_sel[2], 1024);
  for (int i = t; i < mm; i += NT) {
    unsigned vi = tie_v[i]; unsigned ni = tie_p[i] >> 16; int rank = 0;
    for (int j = 0; j < mm; j++) {
      unsigned vj = tie_v[j];
      if (vj > vi || (vj == vi && (tie_p[j] >> 16) < ni)) rank++;
    }
    if (rank >= r) lbl[tie_p[i] & 0xFFFFu] = -1.f;
  }
  __syncthreads();
}

// grid (BB, 2): blockIdx.y==0 -> fg select; ==1 -> bg select (+uw). Independent.
__global__ __launch_bounds__(NT) void subsample_kernel() {
  int b = blockIdx.x; int cat = blockIdx.y; int t = threadIdx.x;
  __shared__ unsigned tie_v[1024];
  __shared__ unsigned tie_p[1024];
  __shared__ int wsum[32];
  __shared__ int s_sel[3];
  float* lbl = g_lbl + b*NN;
  int fgc = g_cnt[b*2], bgc = g_cnt[b*2 + 1];
  int fg_kept = min(fgc, 128);
  if (cat == 0) {
    if (fgc > 128)
      select_top(lbl, g_cand + (b*2)*NN, g_hist + (b*2)*4096, fgc, 128,
                 tie_v, tie_p, wsum, s_sel, t);
  } else {
    int limit = 256 - fg_kept;
    if (bgc > limit)
      select_top(lbl, g_cand + (b*2 + 1)*NN, g_hist + (b*2 + 1)*4096, bgc, limit,
                 tie_v, tie_p, wsum, s_sel, t);
    if (t == 0) g_uw[b] = 1.f / (float)(fg_kept + min(bgc, limit));
  }
}

// scalar form (R9): 30 regs, high occupancy
__global__ void output_kernel(const float* __restrict__ gt,
                              const float* __restrict__ iminfo,
                              float* __restrict__ out) {
  int idx = blockIdx.x * 256 + threadIdx.x;      // exactly LBL_SZ threads
  int s = idx & (HWV - 1);
  int t12 = idx >> 12;
  int a = t12 % AA;
  int b = t12 / AA;
  float imh = iminfo[0], imw = iminfo[1];
  float fx = (float)((s & 63) * 16);
  float fy = (float)((s >> 6) * 16);
  float ax1 = c_anch[a][0] + fx, ay1 = c_anch[a][1] + fy;
  float ax2 = c_anch[a][2] + fx, ay2 = c_anch[a][3] + fy;
  bool inside = (ax1 >= 0.f) && (ay1 >= 0.f) && (ax2 < imw) && (ay2 < imh);
  float lbl = g_lbl[idx];                        // m-layout == output labels layout
  int arg = (int)g_arg[idx];
  const float* g = gt + (b*KG + arg)*5;
  float aw = ax2 - ax1 + 1.f, ah = ay2 - ay1 + 1.f;
  float acx = ax1 + 0.5f*(aw - 1.f), acy = ay1 + 0.5f*(ah - 1.f);
  float gw = g[2] - g[0] + 1.f, gh = g[3] - g[1] + 1.f;
  float gcx = g[0] + 0.5f*(gw - 1.f), gcy = g[1] + 0.5f*(gh - 1.f);
  float t0 = (gcx - acx) / aw;
  float t1 = (gcy - acy) / ah;
  float t2 = logf(gw / aw);
  float t3 = logf(gh / ah);
  float inw = (lbl == 1.f) ? 1.f : 0.f;
  float ow  = (lbl == 1.f || lbl == 0.f) ? g_uw[b] : 0.f;
  if (!inside) { t0 = t1 = t2 = t3 = 0.f; inw = 0.f; ow = 0.f; lbl = 0.f; }
  out[idx] = lbl;
  int cb = (b*36 + a*4)*HWV + s;
  float tv[4] = {t0, t1, t2, t3};
#pragma unroll
  for (int c4 = 0; c4 < 4; c4++) {
    out[LBL_SZ            + cb + c4*HWV] = tv[c4];
    out[LBL_SZ +   CH_SZ  + cb + c4*HWV] = inw;
    out[LBL_SZ + 2*CH_SZ  + cb + c4*HWV] = ow;
  }
}

// ---------------- host --------------------------------------------------------
extern "C" void kernel_launch(void* const* d_in, const int* in_sizes, int n_in,
                              void* d_out, int out_size) {
  const float* gt     = (const float*)d_in[1];   // (B,50,5)
  const float* iminfo = (const float*)d_in[2];   // (B,2), ref uses row 0
  float* out = (float*)d_out;

  Keys keys;
  for (int b = 0; b < BB; b++) {
#if JAX_PARTITIONABLE
    unsigned b0, b1; tf2x32(0u, 42u, 0u, (unsigned)b, b0, b1);
    unsigned f0, f1, g0, g1;
    tf2x32(b0, b1, 0u, 0u, f0, f1);
    tf2x32(b0, b1, 0u, 1u, g0, g1);
    keys.k[b][0] = f0; keys.k[b][1] = f1; keys.k[b][2] = g0; keys.k[b][3] = g1;
#else
    unsigned y0[16], y1[16], flat[32];
    for (int i = 0; i < 16; i++) tf2x32(0u, 42u, (unsigned)i, (unsigned)(i+16), y0[i], y1[i]);
    for (int i = 0; i < 16; i++) { flat[i] = y0[i]; flat[16+i] = y1[i]; }
    unsigned kb0 = flat[2*b], kb1 = flat[2*b+1];
    unsigned p00, p01, p10, p11;
    tf2x32(kb0, kb1, 0u, 2u, p00, p01);
    tf2x32(kb0, kb1, 1u, 3u, p10, p11);
    keys.k[b][0] = p00; keys.k[b][1] = p10;
    keys.k[b][2] = p01; keys.k[b][3] = p11;
#endif
  }

  fused_kernel<<<dim3(NBLK, BB), 256>>>(gt, iminfo, keys);
  subsample_kernel<<<dim3(BB, 2), NT>>>();
  output_kernel<<<LBL_SZ/256, 256>>>(gt, iminfo, out);
}